// round 8
// baseline (speedup 1.0000x reference)
#include <cuda_runtime.h>
#include <cuda_bf16.h>
#include <mma.h>
#include <math.h>
#include <cstdint>

using namespace nvcuda;

// ---------------- problem constants ----------------
#define NN      10000
#define EE      160000
#define ETOT    170000
#define NH      8
#define C1      30
#define C2      64
#define HC1     240
#define HC2     512
#define FIN     512
#define NCLS    64

// ---------------- device scratch ----------------
__device__ int   g_src[EE];
__device__ int   g_dst[EE];
__device__ int   g_cnt[NN];          // zero at entry (k_scan re-zeroes)
__device__ int   g_off[NN + 1];
__device__ int   g_cur[NN];
__device__ int   g_csr[ETOT];
__device__ float g_feat1[NN * HC1];  // zeroed by k_pre (split-K atomic target)
__device__ float g_as1[NN * NH];
__device__ float g_ad1[NN * NH];
__device__ float g_h1[NN * HC1];     // tf32-rounded ELU output
__device__ float g_feat2[NN * HC2];
__device__ float g_as2[NN * NH];
__device__ float g_ad2[NN * NH];
__device__ float g_xr [NN * FIN];    // tf32-rounded x
__device__ float g_w1r[FIN * HC1];
__device__ float g_w2r[HC1 * HC2];
__device__ float g_wlr[HC2 * NCLS];
__device__ float g_h2r[NN * HC2];    // tf32-rounded copy of out_h

// ---------------- helpers ----------------
__device__ __forceinline__ unsigned encodeF(float f) {
    unsigned u = __float_as_uint(f);
    return (u & 0x80000000u) ? ~u : (u | 0x80000000u);
}
__device__ __forceinline__ float decodeF(unsigned e) {
    return (e & 0x80000000u) ? __uint_as_float(e ^ 0x80000000u)
                             : __uint_as_float(~e);
}
__device__ __forceinline__ float to_tf32(float f) {
    float o;
    asm("cvt.rna.tf32.f32 %0, %1;" : "=f"(o) : "f"(f));
    return o;
}
__device__ __forceinline__ uint32_t smem_u32(const void* p) {
    uint32_t a;
    asm("{ .reg .u64 t; cvta.to.shared.u64 t, %1; cvt.u32.u64 %0, t; }"
        : "=r"(a) : "l"(p));
    return a;
}
__device__ __forceinline__ void cp16(uint32_t dst, const void* src, bool pred) {
    asm volatile("cp.async.cg.shared.global [%0], [%1], 16, %2;"
                 :: "r"(dst), "l"(src), "r"(pred ? 16 : 0));
}
#define CP_COMMIT() asm volatile("cp.async.commit_group;" ::: "memory")
#define CP_WAIT(N)  asm volatile("cp.async.wait_group %0;" :: "n"(N) : "memory")

// ---------------- preprocessing (3 launches) ----------------
#define RX   (NN * FIN)
#define RW1  (FIN * HC1)
#define RW2  (HC1 * HC2)
#define RWL  (HC2 * NCLS)
#define RTOT (RX + RW1 + RW2 + RWL)
#define ZF1  (NN * HC1)

__global__ void k_pre(const void* __restrict__ eraw,
                      const float* __restrict__ x,
                      const float* __restrict__ W1,
                      const float* __restrict__ W2,
                      const float* __restrict__ Wlin)
{
    __shared__ int sh_flag;
    if (threadIdx.x == 0) {
        const int* p = (const int*)eraw;
        int f = 0;
#pragma unroll
        for (int t = 0; t < 64; t++) f |= p[2 * t + 1];
        sh_flag = (f != 0);
    }
    __syncthreads();
    const int i = blockIdx.x * blockDim.x + threadIdx.x;
    const int nt = gridDim.x * blockDim.x;
    if (i < EE) {
        int s, d;
        if (sh_flag) {
            const int* p = (const int*)eraw;
            s = p[i]; d = p[EE + i];
        } else {
            const long long* p = (const long long*)eraw;
            s = (int)p[i]; d = (int)p[EE + i];
        }
        g_src[i] = s;
        g_dst[i] = d;
        atomicAdd(&g_cnt[d], 1);
    }
    for (int j = i; j < RTOT; j += nt) {
        if (j < RX)                  g_xr[j]  = to_tf32(x[j]);
        else if (j < RX + RW1)       g_w1r[j - RX] = to_tf32(W1[j - RX]);
        else if (j < RX + RW1 + RW2) g_w2r[j - RX - RW1] = to_tf32(W2[j - RX - RW1]);
        else                         g_wlr[j - RX - RW1 - RW2] = to_tf32(Wlin[j - RX - RW1 - RW2]);
    }
    for (int j = i; j < ZF1; j += nt) g_feat1[j] = 0.f;
}
__global__ void k_scan() {
    __shared__ int ps[257];
    const int CHUNK = 40;
    int t = threadIdx.x;
    int s = 0;
    for (int k = 0; k < CHUNK; k++) {
        int idx = t * CHUNK + k;
        if (idx < NN) s += g_cnt[idx] + 1;
    }
    ps[t] = s;
    __syncthreads();
    if (t == 0) {
        int run = 0;
        for (int i = 0; i < 256; i++) { int tmp = ps[i]; ps[i] = run; run += tmp; }
        ps[256] = run;
    }
    __syncthreads();
    int run = ps[t];
    for (int k = 0; k < CHUNK; k++) {
        int idx = t * CHUNK + k;
        if (idx < NN) {
            g_off[idx] = run;
            g_cur[idx] = run;
            run += g_cnt[idx] + 1;
            g_cnt[idx] = 0;
        }
    }
    if (t == 0) g_off[NN] = ps[256];
}
__global__ void k_scatter(float* __restrict__ out_cls,
                          const float* __restrict__ blin)
{
    const int i = blockIdx.x * blockDim.x + threadIdx.x;
    const int nt = gridDim.x * blockDim.x;
    if (i < ETOT) {
        int d, s;
        if (i < EE) { d = g_dst[i]; s = g_src[i]; }
        else        { d = i - EE;   s = d; }
        int pos = atomicAdd(&g_cur[d], 1);
        g_csr[pos] = s;
    }
    for (int j = i; j < NN * NCLS; j += nt)
        out_cls[j] = blin[j & (NCLS - 1)];
}

// ---------------- 64x64 cp.async tf32 WMMA GEMM (3-stage, high-occ) ----------------
template<bool ATOMIC>
__global__ __launch_bounds__(128, 8) void k_gemm64(
    const float* __restrict__ A, const float* __restrict__ B,
    float* __restrict__ C, int M, int Nc, int K, int klen)
{
    constexpr int LDA = 20, LDB = 68;
    constexpr int ABYT = 64 * LDA * 4;
    constexpr int BBYT = 16 * LDB * 4;
    __shared__ float As[3][64 * LDA];
    __shared__ float Bs[3][16 * LDB];

    const int tid  = threadIdx.x;
    const int warp = tid >> 5, lane = tid & 31;
    const int wm = warp >> 1, wn = warp & 1;
    const int row0  = blockIdx.y * 64;
    const int col0  = blockIdx.x * 64;
    const int kbase = blockIdx.z * klen;
    float* stage = ((float*)As) + warp * 320;   // epilogue alias

    const uint32_t aBase = smem_u32(As), bBase = smem_u32(Bs);
    bool apred[2]; const float* asp[2]; uint32_t adst[2];
#pragma unroll
    for (int v = 0; v < 2; v++) {
        int idx = tid + v * 128;
        int r = idx >> 2, c4 = idx & 3;
        apred[v] = (row0 + r < M);
        asp[v]   = A + (size_t)(apred[v] ? row0 + r : 0) * K + kbase + c4 * 4;
        adst[v]  = aBase + (uint32_t)(r * LDA + c4 * 4) * 4;
    }
    bool bpred[2]; const float* bsp[2]; uint32_t bdst[2];
#pragma unroll
    for (int v = 0; v < 2; v++) {
        int idx = tid + v * 128;
        int r = idx >> 4, c4 = idx & 15;
        int bcol = col0 + c4 * 4;
        bpred[v] = (bcol + 3 < Nc);
        bsp[v]   = B + (size_t)(kbase + r) * Nc + (bpred[v] ? bcol : 0);
        bdst[v]  = bBase + (uint32_t)(r * LDB + c4 * 4) * 4;
    }

    wmma::fragment<wmma::accumulator, 16, 16, 8, float> acc[2][2];
#pragma unroll
    for (int i = 0; i < 2; i++)
#pragma unroll
        for (int j = 0; j < 2; j++) wmma::fill_fragment(acc[i][j], 0.f);

    const int nk = klen / 16;

#define ISSUE(S) do {                                                        \
        const int _s = (S);                                                  \
        const uint32_t _buf = (uint32_t)(_s % 3);                            \
        cp16(adst[0] + _buf * ABYT, asp[0] + (size_t)_s * 16, apred[0]);     \
        cp16(adst[1] + _buf * ABYT, asp[1] + (size_t)_s * 16, apred[1]);     \
        cp16(bdst[0] + _buf * BBYT, bsp[0] + (size_t)_s * 16 * Nc, bpred[0]);\
        cp16(bdst[1] + _buf * BBYT, bsp[1] + (size_t)_s * 16 * Nc, bpred[1]);\
        CP_COMMIT();                                                         \
    } while (0)

    ISSUE(0);
    if (nk > 1) ISSUE(1); else CP_COMMIT();

    for (int it = 0; it < nk; it++) {
        CP_WAIT(1);
        __syncthreads();
        const int cur = it % 3;
#pragma unroll
        for (int ks = 0; ks < 16; ks += 8) {
            wmma::fragment<wmma::matrix_a, 16, 16, 8, wmma::precision::tf32,
                           wmma::row_major> fa[2];
            wmma::fragment<wmma::matrix_b, 16, 16, 8, wmma::precision::tf32,
                           wmma::row_major> fb[2];
#pragma unroll
            for (int i = 0; i < 2; i++)
                wmma::load_matrix_sync(fa[i],
                    &As[cur][(wm * 32 + 16 * i) * LDA + ks], LDA);
#pragma unroll
            for (int j = 0; j < 2; j++)
                wmma::load_matrix_sync(fb[j],
                    &Bs[cur][ks * LDB + wn * 32 + 16 * j], LDB);
#pragma unroll
            for (int i = 0; i < 2; i++)
#pragma unroll
                for (int j = 0; j < 2; j++)
                    wmma::mma_sync(acc[i][j], fa[i], fb[j], acc[i][j]);
        }
        __syncthreads();     // stage consumed before refill
        if (it + 2 < nk) ISSUE(it + 2); else CP_COMMIT();
    }
#undef ISSUE

    if (!ATOMIC && (row0 + 64 <= M) && (col0 + 64 <= Nc)) {
#pragma unroll
        for (int i = 0; i < 2; i++)
#pragma unroll
            for (int j = 0; j < 2; j++) {
                float* cp = C + (size_t)(row0 + wm * 32 + 16 * i) * Nc
                              + col0 + wn * 32 + 16 * j;
                wmma::store_matrix_sync(cp, acc[i][j], Nc, wmma::mem_row_major);
            }
    } else {
        __syncthreads();
#pragma unroll
        for (int i = 0; i < 2; i++)
#pragma unroll
            for (int j = 0; j < 2; j++) {
                wmma::store_matrix_sync(stage, acc[i][j], 20, wmma::mem_row_major);
                __syncwarp();
#pragma unroll
                for (int e = 0; e < 8; e++) {
                    int idx = lane + e * 32;
                    int r = idx >> 4, c = idx & 15;
                    int gr = row0 + wm * 32 + 16 * i + r;
                    int gc = col0 + wn * 32 + 16 * j + c;
                    if (gr < M && gc < Nc) {
                        if (ATOMIC)
                            atomicAdd(&C[(size_t)gr * Nc + gc], stage[r * 20 + c]);
                        else
                            C[(size_t)gr * Nc + gc] = stage[r * 20 + c];
                    }
                }
                __syncwarp();
            }
    }
}

// ---------------- attention projections ----------------
template<int C>
__global__ void k_att(const float* __restrict__ feat,
                      const float* __restrict__ a_src,
                      const float* __restrict__ a_dst,
                      float* __restrict__ asrc,
                      float* __restrict__ adst)
{
    int idx = blockIdx.x * blockDim.x + threadIdx.x;
    if (idx >= NN * NH) return;
    int n = idx >> 3, h = idx & 7;
    const float* fr = feat + (size_t)n * (NH * C) + h * C;
    float ss = 0.f, sd = 0.f;
#pragma unroll
    for (int c = 0; c < C; c++) {
        float f = fr[c];
        ss += f * a_src[h * C + c];
        sd += f * a_dst[h * C + c];
    }
    asrc[idx] = ss;
    adst[idx] = sd;
}

// ---------------- per-destination GAT aggregation ----------------
// Fast path (deg<=64): warp w owns head w; shfl reductions, no smem atomics.
template<int C, bool ELU, bool RND>
__global__ __launch_bounds__(256) void k_agg(
    const float* __restrict__ feat,
    const float* __restrict__ asrc,
    const float* __restrict__ adst,
    const float* __restrict__ bias,
    float* __restrict__ out,
    float* __restrict__ out2)
{
    constexpr int HC  = NH * C;
    constexpr int NV4 = HC / 4;
    constexpr int EP  = 256 / NV4;
    __shared__ float    s_adst[NH];
    __shared__ unsigned s_max[NH];
    __shared__ float    s_sum[NH];
    __shared__ float    s_rs[NH];
    __shared__ int      s_src[64];
    __shared__ float    s_w[64 * NH];
    __shared__ float4   s_red[256];

    const int n = blockIdx.x, tid = threadIdx.x;
    const int warp = tid >> 5, lane = tid & 31;

    const int base = g_off[n];
    const int deg  = g_off[n + 1] - base;

    const int grp  = tid / NV4;
    const int col4 = tid - grp * NV4;
    const int cb   = col4 * 4;
    const int h0 = (cb + 0) / C, h1 = (cb + 1) / C,
              h2 = (cb + 2) / C, h3 = (cb + 3) / C;
    float4 acc = make_float4(0.f, 0.f, 0.f, 0.f);

    if (deg <= 64) {
        // ---- warp-per-head softmax, shfl reductions ----
        if (tid < deg) s_src[tid] = g_csr[base + tid];
        __syncthreads();
        const float ad = adst[n * NH + warp];
        float al0 = -3.4e38f, al1 = -3.4e38f;
        int j0 = lane, j1 = lane + 32;
        if (j0 < deg) {
            float a = asrc[s_src[j0] * NH + warp] + ad;
            al0 = a > 0.f ? a : 0.2f * a;
        }
        if (j1 < deg) {
            float a = asrc[s_src[j1] * NH + warp] + ad;
            al1 = a > 0.f ? a : 0.2f * a;
        }
        float m = fmaxf(al0, al1);
#pragma unroll
        for (int o = 16; o > 0; o >>= 1)
            m = fmaxf(m, __shfl_xor_sync(0xFFFFFFFFu, m, o));
        float e0 = (j0 < deg) ? __expf(al0 - m) : 0.f;
        float e1 = (j1 < deg) ? __expf(al1 - m) : 0.f;
        float s = e0 + e1;
#pragma unroll
        for (int o = 16; o > 0; o >>= 1)
            s += __shfl_xor_sync(0xFFFFFFFFu, s, o);
        const float rs = 1.f / (s + 1e-16f);
        if (j0 < deg) s_w[(j0 << 3) + warp] = e0 * rs;
        if (j1 < deg) s_w[(j1 << 3) + warp] = e1 * rs;
        __syncthreads();

        if (grp < EP) {
            for (int j = grp; j < deg; j += EP) {
                const float4 f = *(const float4*)(feat + (size_t)s_src[j] * HC + cb);
                const float* w = &s_w[j << 3];
                acc.x += w[h0] * f.x;
                acc.y += w[h1] * f.y;
                acc.z += w[h2] * f.z;
                acc.w += w[h3] * f.w;
            }
        }
    } else {
        // ---- general path ----
        if (tid < NH) {
            s_adst[tid] = adst[n * NH + tid];
            s_max[tid]  = encodeF(-3.4e38f);
            s_sum[tid]  = 0.f;
        }
        __syncthreads();
        for (int i = tid; i < deg * NH; i += 256) {
            int j = i >> 3, h = i & 7;
            float al = asrc[g_csr[base + j] * NH + h] + s_adst[h];
            al = al > 0.f ? al : 0.2f * al;
            atomicMax(&s_max[h], encodeF(al));
        }
        __syncthreads();
        for (int i = tid; i < deg * NH; i += 256) {
            int j = i >> 3, h = i & 7;
            float al = asrc[g_csr[base + j] * NH + h] + s_adst[h];
            al = al > 0.f ? al : 0.2f * al;
            atomicAdd(&s_sum[h], __expf(al - decodeF(s_max[h])));
        }
        __syncthreads();
        if (tid < NH) s_rs[tid] = 1.f / (s_sum[tid] + 1e-16f);
        __syncthreads();
        for (int j0 = 0; j0 < deg; j0 += 64) {
            int nch = min(64, deg - j0);
            if (tid < nch) s_src[tid] = g_csr[base + j0 + tid];
            for (int i = tid; i < nch * NH; i += 256) {
                int j = i >> 3, h = i & 7;
                float al = asrc[g_csr[base + j0 + j] * NH + h] + s_adst[h];
                al = al > 0.f ? al : 0.2f * al;
                s_w[i] = __expf(al - decodeF(s_max[h])) * s_rs[h];
            }
            __syncthreads();
            if (grp < EP) {
                for (int j = grp; j < nch; j += EP) {
                    const float4 f = *(const float4*)(feat + (size_t)s_src[j] * HC + cb);
                    const float* w = &s_w[j << 3];
                    acc.x += w[h0] * f.x;
                    acc.y += w[h1] * f.y;
                    acc.z += w[h2] * f.z;
                    acc.w += w[h3] * f.w;
                }
            }
            __syncthreads();
        }
    }

    s_red[tid] = acc;
    __syncthreads();
    if (tid < NV4) {
        float4 a = s_red[tid];
#pragma unroll
        for (int g = 1; g < EP; g++) {
            float4 b = s_red[tid + g * NV4];
            a.x += b.x; a.y += b.y; a.z += b.z; a.w += b.w;
        }
        const float4 bb = *(const float4*)(bias + cb);
        a.x += bb.x; a.y += bb.y; a.z += bb.z; a.w += bb.w;
        if (ELU) {
            a.x = a.x > 0.f ? a.x : (__expf(a.x) - 1.f);
            a.y = a.y > 0.f ? a.y : (__expf(a.y) - 1.f);
            a.z = a.z > 0.f ? a.z : (__expf(a.z) - 1.f);
            a.w = a.w > 0.f ? a.w : (__expf(a.w) - 1.f);
        }
        float4 av = a;
        if (RND) {
            av.x = to_tf32(a.x); av.y = to_tf32(a.y);
            av.z = to_tf32(a.z); av.w = to_tf32(a.w);
        }
        *(float4*)(out + (size_t)n * HC + cb) = RND ? av : a;
        if (out2) {
            float4 r;
            r.x = to_tf32(a.x); r.y = to_tf32(a.y);
            r.z = to_tf32(a.z); r.w = to_tf32(a.w);
            *(float4*)(out2 + (size_t)n * HC + cb) = r;
        }
    }
}

// ---------------- launch ----------------
extern "C" void kernel_launch(void* const* d_in, const int* in_sizes, int n_in,
                              void* d_out, int out_size)
{
    const float* x    = (const float*)d_in[0];
    const void*  eidx = d_in[1];
    const float* W1   = (const float*)d_in[2];
    const float* a1s  = (const float*)d_in[3];
    const float* a1d  = (const float*)d_in[4];
    const float* b1   = (const float*)d_in[5];
    const float* W2   = (const float*)d_in[6];
    const float* a2s  = (const float*)d_in[7];
    const float* a2d  = (const float*)d_in[8];
    const float* b2   = (const float*)d_in[9];
    const float* Wlin = (const float*)d_in[10];
    const float* blin = (const float*)d_in[11];

    float* out_cls = (float*)d_out;
    float* out_h   = out_cls + (size_t)NN * NCLS;

    void *p_feat1, *p_as1, *p_ad1, *p_h1, *p_feat2, *p_as2, *p_ad2;
    void *p_xr, *p_w1r, *p_w2r, *p_wlr, *p_h2r;
    cudaGetSymbolAddress(&p_feat1, g_feat1);
    cudaGetSymbolAddress(&p_as1,   g_as1);
    cudaGetSymbolAddress(&p_ad1,   g_ad1);
    cudaGetSymbolAddress(&p_h1,    g_h1);
    cudaGetSymbolAddress(&p_feat2, g_feat2);
    cudaGetSymbolAddress(&p_as2,   g_as2);
    cudaGetSymbolAddress(&p_ad2,   g_ad2);
    cudaGetSymbolAddress(&p_xr,    g_xr);
    cudaGetSymbolAddress(&p_w1r,   g_w1r);
    cudaGetSymbolAddress(&p_w2r,   g_w2r);
    cudaGetSymbolAddress(&p_wlr,   g_wlr);
    cudaGetSymbolAddress(&p_h2r,   g_h2r);

    const int T = 256;

    // preprocessing: 3 launches (GEMM1 keeps the ncu slot = launch #4)
    k_pre    <<<2560, T>>>(eidx, x, W1, W2, Wlin);
    k_scan   <<<1, 256>>>();
    k_scatter<<<2560, T>>>(out_cls, blin);

    // layer 1: feat1 += xr @ W1r   (split-K=2, atomic)
    {
        dim3 grid((HC1 + 63) / 64, (NN + 63) / 64, 2);
        k_gemm64<true><<<grid, 128>>>((const float*)p_xr, (const float*)p_w1r,
                                      (float*)p_feat1, NN, HC1, FIN, FIN / 2);
    }
    k_att<C1><<<(NN * NH + T - 1) / T, T>>>((const float*)p_feat1, a1s, a1d,
                                            (float*)p_as1, (float*)p_ad1);
    k_agg<C1, true, true><<<NN, 256>>>((const float*)p_feat1, (const float*)p_as1,
                                       (const float*)p_ad1, b1, (float*)p_h1,
                                       nullptr);

    // layer 2: feat2 = h1 @ W2r
    {
        dim3 grid((HC2 + 63) / 64, (NN + 63) / 64, 1);
        k_gemm64<false><<<grid, 128>>>((const float*)p_h1, (const float*)p_w2r,
                                       (float*)p_feat2, NN, HC2, HC1, HC1);
    }
    k_att<C2><<<(NN * NH + T - 1) / T, T>>>((const float*)p_feat2, a2s, a2d,
                                            (float*)p_as2, (float*)p_ad2);
    k_agg<C2, false, false><<<NN, 256>>>((const float*)p_feat2, (const float*)p_as2,
                                         (const float*)p_ad2, b2, out_h,
                                         (float*)p_h2r);

    // final linear: out_cls(+bias init) += h2r @ Wlr  (split-K=4, atomic)
    {
        dim3 grid((NCLS + 63) / 64, (NN + 63) / 64, 4);
        k_gemm64<true><<<grid, 128>>>((const float*)p_h2r, (const float*)p_wlr,
                                      out_cls, NN, NCLS, HC2, HC2 / 4);
    }
}

// round 9
// speedup vs baseline: 1.1912x; 1.1912x over previous
#include <cuda_runtime.h>
#include <cuda_bf16.h>
#include <mma.h>
#include <math.h>
#include <cstdint>

using namespace nvcuda;

// ---------------- problem constants ----------------
#define NN      10000
#define EE      160000
#define ETOT    170000
#define NH      8
#define C1      30
#define C2      64
#define HC1     240
#define HC2     512
#define FIN     512
#define NCLS    64

// ---------------- device scratch ----------------
__device__ int   g_src[EE];
__device__ int   g_dst[EE];
__device__ int   g_cnt[NN];          // zero at entry (k_scan re-zeroes)
__device__ int   g_off[NN + 1];
__device__ int   g_cur[NN];
__device__ int   g_csr[ETOT];
__device__ float g_feat1[NN * HC1];  // zeroed by k_pre (split-K atomic target)
__device__ float g_as1[NN * NH];
__device__ float g_ad1[NN * NH];
__device__ float g_h1[NN * HC1];     // tf32-rounded ELU output
__device__ float g_feat2[NN * HC2];
__device__ float g_as2[NN * NH];
__device__ float g_ad2[NN * NH];
__device__ float g_xr [NN * FIN];    // tf32-rounded x
__device__ float g_w1r[FIN * HC1];
__device__ float g_w2r[HC1 * HC2];
__device__ float g_wlr[HC2 * NCLS];
__device__ float g_h2r[NN * HC2];    // tf32-rounded copy of out_h

// ---------------- helpers ----------------
__device__ __forceinline__ unsigned encodeF(float f) {
    unsigned u = __float_as_uint(f);
    return (u & 0x80000000u) ? ~u : (u | 0x80000000u);
}
__device__ __forceinline__ float decodeF(unsigned e) {
    return (e & 0x80000000u) ? __uint_as_float(e ^ 0x80000000u)
                             : __uint_as_float(~e);
}
__device__ __forceinline__ float to_tf32(float f) {
    float o;
    asm("cvt.rna.tf32.f32 %0, %1;" : "=f"(o) : "f"(f));
    return o;
}
__device__ __forceinline__ uint32_t smem_u32(const void* p) {
    uint32_t a;
    asm("{ .reg .u64 t; cvta.to.shared.u64 t, %1; cvt.u32.u64 %0, t; }"
        : "=r"(a) : "l"(p));
    return a;
}
__device__ __forceinline__ void cp16(uint32_t dst, const void* src, bool pred) {
    asm volatile("cp.async.cg.shared.global [%0], [%1], 16, %2;"
                 :: "r"(dst), "l"(src), "r"(pred ? 16 : 0));
}
#define CP_COMMIT() asm volatile("cp.async.commit_group;" ::: "memory")
#define CP_WAIT(N)  asm volatile("cp.async.wait_group %0;" :: "n"(N) : "memory")

// ---------------- preprocessing (3 launches) ----------------
#define RX   (NN * FIN)
#define RW1  (FIN * HC1)
#define RW2  (HC1 * HC2)
#define RWL  (HC2 * NCLS)
#define RTOT (RX + RW1 + RW2 + RWL)
#define ZF1  (NN * HC1)

__global__ void k_pre(const void* __restrict__ eraw,
                      const float* __restrict__ x,
                      const float* __restrict__ W1,
                      const float* __restrict__ W2,
                      const float* __restrict__ Wlin)
{
    __shared__ int sh_flag;
    if (threadIdx.x == 0) {
        const int* p = (const int*)eraw;
        int f = 0;
#pragma unroll
        for (int t = 0; t < 64; t++) f |= p[2 * t + 1];
        sh_flag = (f != 0);
    }
    __syncthreads();
    const int i = blockIdx.x * blockDim.x + threadIdx.x;
    const int nt = gridDim.x * blockDim.x;
    if (i < EE) {
        int s, d;
        if (sh_flag) {
            const int* p = (const int*)eraw;
            s = p[i]; d = p[EE + i];
        } else {
            const long long* p = (const long long*)eraw;
            s = (int)p[i]; d = (int)p[EE + i];
        }
        g_src[i] = s;
        g_dst[i] = d;
        atomicAdd(&g_cnt[d], 1);
    }
    for (int j = i; j < RTOT; j += nt) {
        if (j < RX)                  g_xr[j]  = to_tf32(x[j]);
        else if (j < RX + RW1)       g_w1r[j - RX] = to_tf32(W1[j - RX]);
        else if (j < RX + RW1 + RW2) g_w2r[j - RX - RW1] = to_tf32(W2[j - RX - RW1]);
        else                         g_wlr[j - RX - RW1 - RW2] = to_tf32(Wlin[j - RX - RW1 - RW2]);
    }
    for (int j = i; j < ZF1; j += nt) g_feat1[j] = 0.f;
}
__global__ void k_scan() {
    __shared__ int ps[257];
    const int CHUNK = 40;
    int t = threadIdx.x;
    int s = 0;
    for (int k = 0; k < CHUNK; k++) {
        int idx = t * CHUNK + k;
        if (idx < NN) s += g_cnt[idx] + 1;
    }
    ps[t] = s;
    __syncthreads();
    if (t == 0) {
        int run = 0;
        for (int i = 0; i < 256; i++) { int tmp = ps[i]; ps[i] = run; run += tmp; }
        ps[256] = run;
    }
    __syncthreads();
    int run = ps[t];
    for (int k = 0; k < CHUNK; k++) {
        int idx = t * CHUNK + k;
        if (idx < NN) {
            g_off[idx] = run;
            g_cur[idx] = run;
            run += g_cnt[idx] + 1;
            g_cnt[idx] = 0;
        }
    }
    if (t == 0) g_off[NN] = ps[256];
}
__global__ void k_scatter(float* __restrict__ out_cls,
                          const float* __restrict__ blin)
{
    const int i = blockIdx.x * blockDim.x + threadIdx.x;
    const int nt = gridDim.x * blockDim.x;
    if (i < ETOT) {
        int d, s;
        if (i < EE) { d = g_dst[i]; s = g_src[i]; }
        else        { d = i - EE;   s = d; }
        int pos = atomicAdd(&g_cur[d], 1);
        g_csr[pos] = s;
    }
    for (int j = i; j < NN * NCLS; j += nt)
        out_cls[j] = blin[j & (NCLS - 1)];
}

// ---------------- 64x64 cp.async tf32 WMMA GEMM (R7 config: 4-stage, occ 6) ----------------
template<bool ATOMIC>
__global__ __launch_bounds__(128, 6) void k_gemm64(
    const float* __restrict__ A, const float* __restrict__ B,
    float* __restrict__ C, int M, int Nc, int K, int klen)
{
    constexpr int LDA = 20, LDB = 68;
    constexpr int ABYT = 64 * LDA * 4;
    constexpr int BBYT = 16 * LDB * 4;
    __shared__ float As[4][64 * LDA];
    __shared__ float Bs[4][16 * LDB];

    const int tid  = threadIdx.x;
    const int warp = tid >> 5, lane = tid & 31;
    const int wm = warp >> 1, wn = warp & 1;
    const int row0  = blockIdx.y * 64;
    const int col0  = blockIdx.x * 64;
    const int kbase = blockIdx.z * klen;
    float* stage = ((float*)As) + warp * 320;   // epilogue alias

    const uint32_t aBase = smem_u32(As), bBase = smem_u32(Bs);
    bool apred[2]; const float* asp[2]; uint32_t adst[2];
#pragma unroll
    for (int v = 0; v < 2; v++) {
        int idx = tid + v * 128;
        int r = idx >> 2, c4 = idx & 3;
        apred[v] = (row0 + r < M);
        asp[v]   = A + (size_t)(apred[v] ? row0 + r : 0) * K + kbase + c4 * 4;
        adst[v]  = aBase + (uint32_t)(r * LDA + c4 * 4) * 4;
    }
    bool bpred[2]; const float* bsp[2]; uint32_t bdst[2];
#pragma unroll
    for (int v = 0; v < 2; v++) {
        int idx = tid + v * 128;
        int r = idx >> 4, c4 = idx & 15;
        int bcol = col0 + c4 * 4;
        bpred[v] = (bcol + 3 < Nc);
        bsp[v]   = B + (size_t)(kbase + r) * Nc + (bpred[v] ? bcol : 0);
        bdst[v]  = bBase + (uint32_t)(r * LDB + c4 * 4) * 4;
    }

    wmma::fragment<wmma::accumulator, 16, 16, 8, float> acc[2][2];
#pragma unroll
    for (int i = 0; i < 2; i++)
#pragma unroll
        for (int j = 0; j < 2; j++) wmma::fill_fragment(acc[i][j], 0.f);

    const int nk = klen / 16;

#define ISSUE(S) do {                                                        \
        const int _s = (S);                                                  \
        const uint32_t _buf = (uint32_t)(_s & 3);                            \
        cp16(adst[0] + _buf * ABYT, asp[0] + (size_t)_s * 16, apred[0]);     \
        cp16(adst[1] + _buf * ABYT, asp[1] + (size_t)_s * 16, apred[1]);     \
        cp16(bdst[0] + _buf * BBYT, bsp[0] + (size_t)_s * 16 * Nc, bpred[0]);\
        cp16(bdst[1] + _buf * BBYT, bsp[1] + (size_t)_s * 16 * Nc, bpred[1]);\
        CP_COMMIT();                                                         \
    } while (0)

#pragma unroll
    for (int s = 0; s < 3; s++) {
        if (s < nk) ISSUE(s); else CP_COMMIT();
    }

    for (int it = 0; it < nk; it++) {
        CP_WAIT(2);
        __syncthreads();
        const int cur = it & 3;
#pragma unroll
        for (int ks = 0; ks < 16; ks += 8) {
            wmma::fragment<wmma::matrix_a, 16, 16, 8, wmma::precision::tf32,
                           wmma::row_major> fa[2];
            wmma::fragment<wmma::matrix_b, 16, 16, 8, wmma::precision::tf32,
                           wmma::row_major> fb[2];
#pragma unroll
            for (int i = 0; i < 2; i++)
                wmma::load_matrix_sync(fa[i],
                    &As[cur][(wm * 32 + 16 * i) * LDA + ks], LDA);
#pragma unroll
            for (int j = 0; j < 2; j++)
                wmma::load_matrix_sync(fb[j],
                    &Bs[cur][ks * LDB + wn * 32 + 16 * j], LDB);
#pragma unroll
            for (int i = 0; i < 2; i++)
#pragma unroll
                for (int j = 0; j < 2; j++)
                    wmma::mma_sync(acc[i][j], fa[i], fb[j], acc[i][j]);
        }
        if (it + 3 < nk) ISSUE(it + 3); else CP_COMMIT();
    }
#undef ISSUE

    if (!ATOMIC && (row0 + 64 <= M) && (col0 + 64 <= Nc)) {
#pragma unroll
        for (int i = 0; i < 2; i++)
#pragma unroll
            for (int j = 0; j < 2; j++) {
                float* cp = C + (size_t)(row0 + wm * 32 + 16 * i) * Nc
                              + col0 + wn * 32 + 16 * j;
                wmma::store_matrix_sync(cp, acc[i][j], Nc, wmma::mem_row_major);
            }
    } else {
        __syncthreads();   // compute done before As reused as stage
#pragma unroll
        for (int i = 0; i < 2; i++)
#pragma unroll
            for (int j = 0; j < 2; j++) {
                wmma::store_matrix_sync(stage, acc[i][j], 20, wmma::mem_row_major);
                __syncwarp();
#pragma unroll
                for (int e = 0; e < 8; e++) {
                    int idx = lane + e * 32;
                    int r = idx >> 4, c = idx & 15;
                    int gr = row0 + wm * 32 + 16 * i + r;
                    int gc = col0 + wn * 32 + 16 * j + c;
                    if (gr < M && gc < Nc) {
                        if (ATOMIC)
                            atomicAdd(&C[(size_t)gr * Nc + gc], stage[r * 20 + c]);
                        else
                            C[(size_t)gr * Nc + gc] = stage[r * 20 + c];
                    }
                }
                __syncwarp();
            }
    }
}

// ---------------- attention projections ----------------
template<int C>
__global__ void k_att(const float* __restrict__ feat,
                      const float* __restrict__ a_src,
                      const float* __restrict__ a_dst,
                      float* __restrict__ asrc,
                      float* __restrict__ adst)
{
    int idx = blockIdx.x * blockDim.x + threadIdx.x;
    if (idx >= NN * NH) return;
    int n = idx >> 3, h = idx & 7;
    const float* fr = feat + (size_t)n * (NH * C) + h * C;
    float ss = 0.f, sd = 0.f;
#pragma unroll
    for (int c = 0; c < C; c++) {
        float f = fr[c];
        ss += f * a_src[h * C + c];
        sd += f * a_dst[h * C + c];
    }
    asrc[idx] = ss;
    adst[idx] = sd;
}

// ---------------- per-destination GAT aggregation ----------------
// Fast path (deg<=64): warp w owns head w; shfl reductions, no smem atomics.
template<int C, bool ELU, bool RND>
__global__ __launch_bounds__(256) void k_agg(
    const float* __restrict__ feat,
    const float* __restrict__ asrc,
    const float* __restrict__ adst,
    const float* __restrict__ bias,
    float* __restrict__ out,
    float* __restrict__ out2)
{
    constexpr int HC  = NH * C;
    constexpr int NV4 = HC / 4;
    constexpr int EP  = 256 / NV4;
    __shared__ float    s_adst[NH];
    __shared__ unsigned s_max[NH];
    __shared__ float    s_sum[NH];
    __shared__ float    s_rs[NH];
    __shared__ int      s_src[64];
    __shared__ float    s_w[64 * NH];
    __shared__ float4   s_red[256];

    const int n = blockIdx.x, tid = threadIdx.x;
    const int warp = tid >> 5, lane = tid & 31;

    const int base = g_off[n];
    const int deg  = g_off[n + 1] - base;

    const int grp  = tid / NV4;
    const int col4 = tid - grp * NV4;
    const int cb   = col4 * 4;
    const int h0 = (cb + 0) / C, h1 = (cb + 1) / C,
              h2 = (cb + 2) / C, h3 = (cb + 3) / C;
    float4 acc = make_float4(0.f, 0.f, 0.f, 0.f);

    if (deg <= 64) {
        // ---- warp-per-head softmax, shfl reductions ----
        if (tid < deg) s_src[tid] = g_csr[base + tid];
        __syncthreads();
        const float ad = adst[n * NH + warp];
        float al0 = -3.4e38f, al1 = -3.4e38f;
        int j0 = lane, j1 = lane + 32;
        if (j0 < deg) {
            float a = asrc[s_src[j0] * NH + warp] + ad;
            al0 = a > 0.f ? a : 0.2f * a;
        }
        if (j1 < deg) {
            float a = asrc[s_src[j1] * NH + warp] + ad;
            al1 = a > 0.f ? a : 0.2f * a;
        }
        float m = fmaxf(al0, al1);
#pragma unroll
        for (int o = 16; o > 0; o >>= 1)
            m = fmaxf(m, __shfl_xor_sync(0xFFFFFFFFu, m, o));
        float e0 = (j0 < deg) ? __expf(al0 - m) : 0.f;
        float e1 = (j1 < deg) ? __expf(al1 - m) : 0.f;
        float s = e0 + e1;
#pragma unroll
        for (int o = 16; o > 0; o >>= 1)
            s += __shfl_xor_sync(0xFFFFFFFFu, s, o);
        const float rs = 1.f / (s + 1e-16f);
        if (j0 < deg) s_w[(j0 << 3) + warp] = e0 * rs;
        if (j1 < deg) s_w[(j1 << 3) + warp] = e1 * rs;
        __syncthreads();

        if (grp < EP) {
            for (int j = grp; j < deg; j += EP) {
                const float4 f = *(const float4*)(feat + (size_t)s_src[j] * HC + cb);
                const float* w = &s_w[j << 3];
                acc.x += w[h0] * f.x;
                acc.y += w[h1] * f.y;
                acc.z += w[h2] * f.z;
                acc.w += w[h3] * f.w;
            }
        }
    } else {
        // ---- general path ----
        if (tid < NH) {
            s_adst[tid] = adst[n * NH + tid];
            s_max[tid]  = encodeF(-3.4e38f);
            s_sum[tid]  = 0.f;
        }
        __syncthreads();
        for (int i = tid; i < deg * NH; i += 256) {
            int j = i >> 3, h = i & 7;
            float al = asrc[g_csr[base + j] * NH + h] + s_adst[h];
            al = al > 0.f ? al : 0.2f * al;
            atomicMax(&s_max[h], encodeF(al));
        }
        __syncthreads();
        for (int i = tid; i < deg * NH; i += 256) {
            int j = i >> 3, h = i & 7;
            float al = asrc[g_csr[base + j] * NH + h] + s_adst[h];
            al = al > 0.f ? al : 0.2f * al;
            atomicAdd(&s_sum[h], __expf(al - decodeF(s_max[h])));
        }
        __syncthreads();
        if (tid < NH) s_rs[tid] = 1.f / (s_sum[tid] + 1e-16f);
        __syncthreads();
        for (int j0 = 0; j0 < deg; j0 += 64) {
            int nch = min(64, deg - j0);
            if (tid < nch) s_src[tid] = g_csr[base + j0 + tid];
            for (int i = tid; i < nch * NH; i += 256) {
                int j = i >> 3, h = i & 7;
                float al = asrc[g_csr[base + j0 + j] * NH + h] + s_adst[h];
                al = al > 0.f ? al : 0.2f * al;
                s_w[i] = __expf(al - decodeF(s_max[h])) * s_rs[h];
            }
            __syncthreads();
            if (grp < EP) {
                for (int j = grp; j < nch; j += EP) {
                    const float4 f = *(const float4*)(feat + (size_t)s_src[j] * HC + cb);
                    const float* w = &s_w[j << 3];
                    acc.x += w[h0] * f.x;
                    acc.y += w[h1] * f.y;
                    acc.z += w[h2] * f.z;
                    acc.w += w[h3] * f.w;
                }
            }
            __syncthreads();
        }
    }

    s_red[tid] = acc;
    __syncthreads();
    if (tid < NV4) {
        float4 a = s_red[tid];
#pragma unroll
        for (int g = 1; g < EP; g++) {
            float4 b = s_red[tid + g * NV4];
            a.x += b.x; a.y += b.y; a.z += b.z; a.w += b.w;
        }
        const float4 bb = *(const float4*)(bias + cb);
        a.x += bb.x; a.y += bb.y; a.z += bb.z; a.w += bb.w;
        if (ELU) {
            a.x = a.x > 0.f ? a.x : (__expf(a.x) - 1.f);
            a.y = a.y > 0.f ? a.y : (__expf(a.y) - 1.f);
            a.z = a.z > 0.f ? a.z : (__expf(a.z) - 1.f);
            a.w = a.w > 0.f ? a.w : (__expf(a.w) - 1.f);
        }
        float4 av = a;
        if (RND) {
            av.x = to_tf32(a.x); av.y = to_tf32(a.y);
            av.z = to_tf32(a.z); av.w = to_tf32(a.w);
        }
        *(float4*)(out + (size_t)n * HC + cb) = RND ? av : a;
        if (out2) {
            float4 r;
            r.x = to_tf32(a.x); r.y = to_tf32(a.y);
            r.z = to_tf32(a.z); r.w = to_tf32(a.w);
            *(float4*)(out2 + (size_t)n * HC + cb) = r;
        }
    }
}

// ---------------- launch ----------------
extern "C" void kernel_launch(void* const* d_in, const int* in_sizes, int n_in,
                              void* d_out, int out_size)
{
    const float* x    = (const float*)d_in[0];
    const void*  eidx = d_in[1];
    const float* W1   = (const float*)d_in[2];
    const float* a1s  = (const float*)d_in[3];
    const float* a1d  = (const float*)d_in[4];
    const float* b1   = (const float*)d_in[5];
    const float* W2   = (const float*)d_in[6];
    const float* a2s  = (const float*)d_in[7];
    const float* a2d  = (const float*)d_in[8];
    const float* b2   = (const float*)d_in[9];
    const float* Wlin = (const float*)d_in[10];
    const float* blin = (const float*)d_in[11];

    float* out_cls = (float*)d_out;
    float* out_h   = out_cls + (size_t)NN * NCLS;

    void *p_feat1, *p_as1, *p_ad1, *p_h1, *p_feat2, *p_as2, *p_ad2;
    void *p_xr, *p_w1r, *p_w2r, *p_wlr, *p_h2r;
    cudaGetSymbolAddress(&p_feat1, g_feat1);
    cudaGetSymbolAddress(&p_as1,   g_as1);
    cudaGetSymbolAddress(&p_ad1,   g_ad1);
    cudaGetSymbolAddress(&p_h1,    g_h1);
    cudaGetSymbolAddress(&p_feat2, g_feat2);
    cudaGetSymbolAddress(&p_as2,   g_as2);
    cudaGetSymbolAddress(&p_ad2,   g_ad2);
    cudaGetSymbolAddress(&p_xr,    g_xr);
    cudaGetSymbolAddress(&p_w1r,   g_w1r);
    cudaGetSymbolAddress(&p_w2r,   g_w2r);
    cudaGetSymbolAddress(&p_wlr,   g_wlr);
    cudaGetSymbolAddress(&p_h2r,   g_h2r);

    const int T = 256;

    // preprocessing: 3 launches (GEMM1 keeps the ncu slot = launch #4)
    k_pre    <<<2560, T>>>(eidx, x, W1, W2, Wlin);
    k_scan   <<<1, 256>>>();
    k_scatter<<<2560, T>>>(out_cls, blin);

    // layer 1: feat1 += xr @ W1r   (split-K=2, atomic)
    {
        dim3 grid((HC1 + 63) / 64, (NN + 63) / 64, 2);
        k_gemm64<true><<<grid, 128>>>((const float*)p_xr, (const float*)p_w1r,
                                      (float*)p_feat1, NN, HC1, FIN, FIN / 2);
    }
    k_att<C1><<<(NN * NH + T - 1) / T, T>>>((const float*)p_feat1, a1s, a1d,
                                            (float*)p_as1, (float*)p_ad1);
    k_agg<C1, true, true><<<NN, 256>>>((const float*)p_feat1, (const float*)p_as1,
                                       (const float*)p_ad1, b1, (float*)p_h1,
                                       nullptr);

    // layer 2: feat2 = h1 @ W2r
    {
        dim3 grid((HC2 + 63) / 64, (NN + 63) / 64, 1);
        k_gemm64<false><<<grid, 128>>>((const float*)p_h1, (const float*)p_w2r,
                                       (float*)p_feat2, NN, HC2, HC1, HC1);
    }
    k_att<C2><<<(NN * NH + T - 1) / T, T>>>((const float*)p_feat2, a2s, a2d,
                                            (float*)p_as2, (float*)p_ad2);
    k_agg<C2, false, false><<<NN, 256>>>((const float*)p_feat2, (const float*)p_as2,
                                         (const float*)p_ad2, b2, out_h,
                                         (float*)p_h2r);

    // final linear: out_cls(+bias init) += h2r @ Wlr  (split-K=4, atomic)
    {
        dim3 grid((NCLS + 63) / 64, (NN + 63) / 64, 4);
        k_gemm64<true><<<grid, 128>>>((const float*)p_h2r, (const float*)p_wlr,
                                      out_cls, NN, NCLS, HC2, HC2 / 4);
    }
}

// round 10
// speedup vs baseline: 1.5092x; 1.2670x over previous
#include <cuda_runtime.h>
#include <cuda_fp16.h>
#include <mma.h>
#include <math.h>
#include <cstdint>

using namespace nvcuda;

// ---------------- problem constants ----------------
#define NN      10000
#define EE      160000
#define ETOT    170000
#define NH      8
#define C1      30
#define C2      64
#define HC1     240
#define HC2     512
#define FIN     512
#define NCLS    64

// ---------------- device scratch ----------------
__device__ int    g_src[EE];
__device__ int    g_dst[EE];
__device__ int    g_cnt[NN];          // zero at entry (k_scan re-zeroes)
__device__ int    g_off[NN + 1];
__device__ int    g_cur[NN];
__device__ int    g_csr[ETOT];
__device__ float  g_feat1[NN * HC1];  // zeroed by k_pre (split-K atomic target)
__device__ float  g_as1[NN * NH];
__device__ float  g_ad1[NN * NH];
__device__ float  g_feat2[NN * HC2];
__device__ float  g_as2[NN * NH];
__device__ float  g_ad2[NN * NH];
__device__ __half g_xh [NN * FIN];    // fp16 copies of GEMM operands
__device__ __half g_w1h[FIN * HC1];
__device__ __half g_w2h[HC1 * HC2];
__device__ __half g_wlh[HC2 * NCLS];
__device__ __half g_h1h[NN * HC1];    // fp16 ELU output (feeds GEMM2)
__device__ __half g_h2h[NN * HC2];    // fp16 copy of out_h (feeds GEMM3)

// ---------------- helpers ----------------
__device__ __forceinline__ unsigned encodeF(float f) {
    unsigned u = __float_as_uint(f);
    return (u & 0x80000000u) ? ~u : (u | 0x80000000u);
}
__device__ __forceinline__ float decodeF(unsigned e) {
    return (e & 0x80000000u) ? __uint_as_float(e ^ 0x80000000u)
                             : __uint_as_float(~e);
}
__device__ __forceinline__ uint32_t smem_u32(const void* p) {
    uint32_t a;
    asm("{ .reg .u64 t; cvta.to.shared.u64 t, %1; cvt.u32.u64 %0, t; }"
        : "=r"(a) : "l"(p));
    return a;
}
__device__ __forceinline__ void cp16(uint32_t dst, const void* src, bool pred) {
    asm volatile("cp.async.cg.shared.global [%0], [%1], 16, %2;"
                 :: "r"(dst), "l"(src), "r"(pred ? 16 : 0));
}
#define CP_COMMIT() asm volatile("cp.async.commit_group;" ::: "memory")
#define CP_WAIT(N)  asm volatile("cp.async.wait_group %0;" :: "n"(N) : "memory")

// ---------------- preprocessing (3 launches) ----------------
#define RX   (NN * FIN)
#define RW1  (FIN * HC1)
#define RW2  (HC1 * HC2)
#define RWL  (HC2 * NCLS)
#define RTOT (RX + RW1 + RW2 + RWL)
#define ZF1  (NN * HC1)

__global__ void k_pre(const void* __restrict__ eraw,
                      const float* __restrict__ x,
                      const float* __restrict__ W1,
                      const float* __restrict__ W2,
                      const float* __restrict__ Wlin)
{
    __shared__ int sh_flag;
    if (threadIdx.x == 0) {
        const int* p = (const int*)eraw;
        int f = 0;
#pragma unroll
        for (int t = 0; t < 64; t++) f |= p[2 * t + 1];
        sh_flag = (f != 0);
    }
    __syncthreads();
    const int i = blockIdx.x * blockDim.x + threadIdx.x;
    const int nt = gridDim.x * blockDim.x;
    if (i < EE) {
        int s, d;
        if (sh_flag) {
            const int* p = (const int*)eraw;
            s = p[i]; d = p[EE + i];
        } else {
            const long long* p = (const long long*)eraw;
            s = (int)p[i]; d = (int)p[EE + i];
        }
        g_src[i] = s;
        g_dst[i] = d;
        atomicAdd(&g_cnt[d], 1);
    }
    for (int j = i; j < RTOT; j += nt) {
        if (j < RX)                  g_xh[j]  = __float2half_rn(x[j]);
        else if (j < RX + RW1)       g_w1h[j - RX] = __float2half_rn(W1[j - RX]);
        else if (j < RX + RW1 + RW2) g_w2h[j - RX - RW1] = __float2half_rn(W2[j - RX - RW1]);
        else                         g_wlh[j - RX - RW1 - RW2] = __float2half_rn(Wlin[j - RX - RW1 - RW2]);
    }
    for (int j = i; j < ZF1; j += nt) g_feat1[j] = 0.f;
}
__global__ void k_scan() {
    __shared__ int ps[257];
    const int CHUNK = 40;
    int t = threadIdx.x;
    int s = 0;
    for (int k = 0; k < CHUNK; k++) {
        int idx = t * CHUNK + k;
        if (idx < NN) s += g_cnt[idx] + 1;
    }
    ps[t] = s;
    __syncthreads();
    if (t == 0) {
        int run = 0;
        for (int i = 0; i < 256; i++) { int tmp = ps[i]; ps[i] = run; run += tmp; }
        ps[256] = run;
    }
    __syncthreads();
    int run = ps[t];
    for (int k = 0; k < CHUNK; k++) {
        int idx = t * CHUNK + k;
        if (idx < NN) {
            g_off[idx] = run;
            g_cur[idx] = run;
            run += g_cnt[idx] + 1;
            g_cnt[idx] = 0;
        }
    }
    if (t == 0) g_off[NN] = ps[256];
}
__global__ void k_scatter(float* __restrict__ out_cls,
                          const float* __restrict__ blin)
{
    const int i = blockIdx.x * blockDim.x + threadIdx.x;
    const int nt = gridDim.x * blockDim.x;
    if (i < ETOT) {
        int d, s;
        if (i < EE) { d = g_dst[i]; s = g_src[i]; }
        else        { d = i - EE;   s = d; }
        int pos = atomicAdd(&g_cur[d], 1);
        g_csr[pos] = s;
    }
    for (int j = i; j < NN * NCLS; j += nt)
        out_cls[j] = blin[j & (NCLS - 1)];
}

// ---------------- 64x64 cp.async fp16 WMMA GEMM (m16n16k16, fp32 acc) ----------------
// A[M,K], B[K,Nc] fp16; C fp32 (+atomic for split-K). 128 thr, 4 warps 2x2,
// warp tile 32x32, BK=16, 4-stage cp.async. klen % 16 == 0, Nc % 8 == 0.
template<bool ATOMIC>
__global__ __launch_bounds__(128, 6) void k_gemm64(
    const __half* __restrict__ A, const __half* __restrict__ B,
    float* __restrict__ C, int M, int Nc, int K, int klen)
{
    constexpr int LDAH = 24, LDBH = 72;              // halves
    constexpr int ABYT = 64 * LDAH * 2;              // 3072 B
    constexpr int BBYT = 16 * LDBH * 2;              // 2304 B
    __shared__ __half As[4][64 * LDAH];
    __shared__ __half Bs[4][16 * LDBH];

    const int tid  = threadIdx.x;
    const int warp = tid >> 5, lane = tid & 31;
    const int wm = warp >> 1, wn = warp & 1;
    const int row0  = blockIdx.y * 64;
    const int col0  = blockIdx.x * 64;
    const int kbase = blockIdx.z * klen;
    float* stage = ((float*)As) + warp * 320;        // epilogue alias (5120 B < ABYT*4)

    const uint32_t aBase = smem_u32(As), bBase = smem_u32(Bs);
    // A: 128 cp16/stage (1 per thread): r = tid>>1, chunk = tid&1 (8 halves each)
    const int ar = tid >> 1, ac = tid & 1;
    const bool apred = (row0 + ar < M);
    const __half* asp = A + (size_t)(apred ? row0 + ar : 0) * K + kbase + ac * 8;
    const uint32_t adst = aBase + (uint32_t)(ar * LDAH + ac * 8) * 2;
    // B: 128 cp16/stage: r = tid>>3, c8 = tid&7
    const int brr = tid >> 3, bc8 = tid & 7;
    const int bcol = col0 + bc8 * 8;
    const bool bpred = (bcol < Nc);                  // Nc multiple of 8
    const __half* bsp = B + (size_t)(kbase + brr) * Nc + (bpred ? bcol : 0);
    const uint32_t bdst = bBase + (uint32_t)(brr * LDBH + bc8 * 8) * 2;

    wmma::fragment<wmma::accumulator, 16, 16, 16, float> acc[2][2];
#pragma unroll
    for (int i = 0; i < 2; i++)
#pragma unroll
        for (int j = 0; j < 2; j++) wmma::fill_fragment(acc[i][j], 0.f);

    const int nk = klen / 16;

#define ISSUE(S) do {                                                        \
        const int _s = (S);                                                  \
        const uint32_t _buf = (uint32_t)(_s & 3);                            \
        cp16(adst + _buf * ABYT, asp + (size_t)_s * 16, apred);              \
        cp16(bdst + _buf * BBYT, bsp + (size_t)_s * 16 * Nc, bpred);         \
        CP_COMMIT();                                                         \
    } while (0)

#pragma unroll
    for (int s = 0; s < 3; s++) {
        if (s < nk) ISSUE(s); else CP_COMMIT();
    }

    for (int it = 0; it < nk; it++) {
        CP_WAIT(2);
        __syncthreads();
        const int cur = it & 3;
        wmma::fragment<wmma::matrix_a, 16, 16, 16, __half, wmma::row_major> fa[2];
        wmma::fragment<wmma::matrix_b, 16, 16, 16, __half, wmma::row_major> fb[2];
#pragma unroll
        for (int i = 0; i < 2; i++)
            wmma::load_matrix_sync(fa[i], &As[cur][(wm * 32 + 16 * i) * LDAH], LDAH);
#pragma unroll
        for (int j = 0; j < 2; j++)
            wmma::load_matrix_sync(fb[j], &Bs[cur][wn * 32 + 16 * j], LDBH);
#pragma unroll
        for (int i = 0; i < 2; i++)
#pragma unroll
            for (int j = 0; j < 2; j++)
                wmma::mma_sync(acc[i][j], fa[i], fb[j], acc[i][j]);
        if (it + 3 < nk) ISSUE(it + 3); else CP_COMMIT();
    }
#undef ISSUE

    if (!ATOMIC && (row0 + 64 <= M) && (col0 + 64 <= Nc)) {
#pragma unroll
        for (int i = 0; i < 2; i++)
#pragma unroll
            for (int j = 0; j < 2; j++) {
                float* cp = C + (size_t)(row0 + wm * 32 + 16 * i) * Nc
                              + col0 + wn * 32 + 16 * j;
                wmma::store_matrix_sync(cp, acc[i][j], Nc, wmma::mem_row_major);
            }
    } else {
        __syncthreads();   // compute done before As reused as stage
#pragma unroll
        for (int i = 0; i < 2; i++)
#pragma unroll
            for (int j = 0; j < 2; j++) {
                wmma::store_matrix_sync(stage, acc[i][j], 20, wmma::mem_row_major);
                __syncwarp();
#pragma unroll
                for (int e = 0; e < 8; e++) {
                    int idx = lane + e * 32;
                    int r = idx >> 4, c = idx & 15;
                    int gr = row0 + wm * 32 + 16 * i + r;
                    int gc = col0 + wn * 32 + 16 * j + c;
                    if (gr < M && gc < Nc) {
                        if (ATOMIC)
                            atomicAdd(&C[(size_t)gr * Nc + gc], stage[r * 20 + c]);
                        else
                            C[(size_t)gr * Nc + gc] = stage[r * 20 + c];
                    }
                }
                __syncwarp();
            }
    }
}

// ---------------- attention projections ----------------
template<int C>
__global__ void k_att(const float* __restrict__ feat,
                      const float* __restrict__ a_src,
                      const float* __restrict__ a_dst,
                      float* __restrict__ asrc,
                      float* __restrict__ adst)
{
    int idx = blockIdx.x * blockDim.x + threadIdx.x;
    if (idx >= NN * NH) return;
    int n = idx >> 3, h = idx & 7;
    const float* fr = feat + (size_t)n * (NH * C) + h * C;
    float ss = 0.f, sd = 0.f;
#pragma unroll
    for (int c = 0; c < C; c++) {
        float f = fr[c];
        ss += f * a_src[h * C + c];
        sd += f * a_dst[h * C + c];
    }
    asrc[idx] = ss;
    adst[idx] = sd;
}

// ---------------- per-destination GAT aggregation ----------------
// Fast path (deg<=64): warp w owns head w; shfl reductions, no smem atomics.
// WRITEF: store fp32 result to outf. outh (optional): fp16 copy.
template<int C, bool ELU, bool WRITEF>
__global__ __launch_bounds__(256) void k_agg(
    const float* __restrict__ feat,
    const float* __restrict__ asrc,
    const float* __restrict__ adst,
    const float* __restrict__ bias,
    float* __restrict__ outf,
    __half* __restrict__ outh)
{
    constexpr int HC  = NH * C;
    constexpr int NV4 = HC / 4;
    constexpr int EP  = 256 / NV4;
    __shared__ float    s_adst[NH];
    __shared__ unsigned s_max[NH];
    __shared__ float    s_sum[NH];
    __shared__ float    s_rs[NH];
    __shared__ int      s_src[64];
    __shared__ float    s_w[64 * NH];
    __shared__ float4   s_red[256];

    const int n = blockIdx.x, tid = threadIdx.x;
    const int warp = tid >> 5, lane = tid & 31;

    const int base = g_off[n];
    const int deg  = g_off[n + 1] - base;

    const int grp  = tid / NV4;
    const int col4 = tid - grp * NV4;
    const int cb   = col4 * 4;
    const int h0 = (cb + 0) / C, h1 = (cb + 1) / C,
              h2 = (cb + 2) / C, h3 = (cb + 3) / C;
    float4 acc = make_float4(0.f, 0.f, 0.f, 0.f);

    if (deg <= 64) {
        if (tid < deg) s_src[tid] = g_csr[base + tid];
        __syncthreads();
        const float ad = adst[n * NH + warp];
        float al0 = -3.4e38f, al1 = -3.4e38f;
        int j0 = lane, j1 = lane + 32;
        if (j0 < deg) {
            float a = asrc[s_src[j0] * NH + warp] + ad;
            al0 = a > 0.f ? a : 0.2f * a;
        }
        if (j1 < deg) {
            float a = asrc[s_src[j1] * NH + warp] + ad;
            al1 = a > 0.f ? a : 0.2f * a;
        }
        float m = fmaxf(al0, al1);
#pragma unroll
        for (int o = 16; o > 0; o >>= 1)
            m = fmaxf(m, __shfl_xor_sync(0xFFFFFFFFu, m, o));
        float e0 = (j0 < deg) ? __expf(al0 - m) : 0.f;
        float e1 = (j1 < deg) ? __expf(al1 - m) : 0.f;
        float s = e0 + e1;
#pragma unroll
        for (int o = 16; o > 0; o >>= 1)
            s += __shfl_xor_sync(0xFFFFFFFFu, s, o);
        const float rs = 1.f / (s + 1e-16f);
        if (j0 < deg) s_w[(j0 << 3) + warp] = e0 * rs;
        if (j1 < deg) s_w[(j1 << 3) + warp] = e1 * rs;
        __syncthreads();

        if (grp < EP) {
            for (int j = grp; j < deg; j += EP) {
                const float4 f = *(const float4*)(feat + (size_t)s_src[j] * HC + cb);
                const float* w = &s_w[j << 3];
                acc.x += w[h0] * f.x;
                acc.y += w[h1] * f.y;
                acc.z += w[h2] * f.z;
                acc.w += w[h3] * f.w;
            }
        }
    } else {
        if (tid < NH) {
            s_adst[tid] = adst[n * NH + tid];
            s_max[tid]  = encodeF(-3.4e38f);
            s_sum[tid]  = 0.f;
        }
        __syncthreads();
        for (int i = tid; i < deg * NH; i += 256) {
            int j = i >> 3, h = i & 7;
            float al = asrc[g_csr[base + j] * NH + h] + s_adst[h];
            al = al > 0.f ? al : 0.2f * al;
            atomicMax(&s_max[h], encodeF(al));
        }
        __syncthreads();
        for (int i = tid; i < deg * NH; i += 256) {
            int j = i >> 3, h = i & 7;
            float al = asrc[g_csr[base + j] * NH + h] + s_adst[h];
            al = al > 0.f ? al : 0.2f * al;
            atomicAdd(&s_sum[h], __expf(al - decodeF(s_max[h])));
        }
        __syncthreads();
        if (tid < NH) s_rs[tid] = 1.f / (s_sum[tid] + 1e-16f);
        __syncthreads();
        for (int j0 = 0; j0 < deg; j0 += 64) {
            int nch = min(64, deg - j0);
            if (tid < nch) s_src[tid] = g_csr[base + j0 + tid];
            for (int i = tid; i < nch * NH; i += 256) {
                int j = i >> 3, h = i & 7;
                float al = asrc[g_csr[base + j0 + j] * NH + h] + s_adst[h];
                al = al > 0.f ? al : 0.2f * al;
                s_w[i] = __expf(al - decodeF(s_max[h])) * s_rs[h];
            }
            __syncthreads();
            if (grp < EP) {
                for (int j = grp; j < nch; j += EP) {
                    const float4 f = *(const float4*)(feat + (size_t)s_src[j] * HC + cb);
                    const float* w = &s_w[j << 3];
                    acc.x += w[h0] * f.x;
                    acc.y += w[h1] * f.y;
                    acc.z += w[h2] * f.z;
                    acc.w += w[h3] * f.w;
                }
            }
            __syncthreads();
        }
    }

    s_red[tid] = acc;
    __syncthreads();
    if (tid < NV4) {
        float4 a = s_red[tid];
#pragma unroll
        for (int g = 1; g < EP; g++) {
            float4 b = s_red[tid + g * NV4];
            a.x += b.x; a.y += b.y; a.z += b.z; a.w += b.w;
        }
        const float4 bb = *(const float4*)(bias + cb);
        a.x += bb.x; a.y += bb.y; a.z += bb.z; a.w += bb.w;
        if (ELU) {
            a.x = a.x > 0.f ? a.x : (__expf(a.x) - 1.f);
            a.y = a.y > 0.f ? a.y : (__expf(a.y) - 1.f);
            a.z = a.z > 0.f ? a.z : (__expf(a.z) - 1.f);
            a.w = a.w > 0.f ? a.w : (__expf(a.w) - 1.f);
        }
        if (WRITEF)
            *(float4*)(outf + (size_t)n * HC + cb) = a;
        if (outh) {
            __half2 lo = __floats2half2_rn(a.x, a.y);
            __half2 hi = __floats2half2_rn(a.z, a.w);
            uint2 pk;
            pk.x = *(uint32_t*)&lo;
            pk.y = *(uint32_t*)&hi;
            *(uint2*)(outh + (size_t)n * HC + cb) = pk;
        }
    }
}

// ---------------- launch ----------------
extern "C" void kernel_launch(void* const* d_in, const int* in_sizes, int n_in,
                              void* d_out, int out_size)
{
    const float* x    = (const float*)d_in[0];
    const void*  eidx = d_in[1];
    const float* W1   = (const float*)d_in[2];
    const float* a1s  = (const float*)d_in[3];
    const float* a1d  = (const float*)d_in[4];
    const float* b1   = (const float*)d_in[5];
    const float* W2   = (const float*)d_in[6];
    const float* a2s  = (const float*)d_in[7];
    const float* a2d  = (const float*)d_in[8];
    const float* b2   = (const float*)d_in[9];
    const float* Wlin = (const float*)d_in[10];
    const float* blin = (const float*)d_in[11];

    float* out_cls = (float*)d_out;
    float* out_h   = out_cls + (size_t)NN * NCLS;

    void *p_feat1, *p_as1, *p_ad1, *p_feat2, *p_as2, *p_ad2;
    void *p_xh, *p_w1h, *p_w2h, *p_wlh, *p_h1h, *p_h2h;
    cudaGetSymbolAddress(&p_feat1, g_feat1);
    cudaGetSymbolAddress(&p_as1,   g_as1);
    cudaGetSymbolAddress(&p_ad1,   g_ad1);
    cudaGetSymbolAddress(&p_feat2, g_feat2);
    cudaGetSymbolAddress(&p_as2,   g_as2);
    cudaGetSymbolAddress(&p_ad2,   g_ad2);
    cudaGetSymbolAddress(&p_xh,    g_xh);
    cudaGetSymbolAddress(&p_w1h,   g_w1h);
    cudaGetSymbolAddress(&p_w2h,   g_w2h);
    cudaGetSymbolAddress(&p_wlh,   g_wlh);
    cudaGetSymbolAddress(&p_h1h,   g_h1h);
    cudaGetSymbolAddress(&p_h2h,   g_h2h);

    const int T = 256;

    // preprocessing: 3 launches (GEMM1 keeps the ncu slot = launch #4)
    k_pre    <<<2560, T>>>(eidx, x, W1, W2, Wlin);
    k_scan   <<<1, 256>>>();
    k_scatter<<<2560, T>>>(out_cls, blin);

    // layer 1: feat1 += xh @ W1h   (split-K=2, atomic)
    {
        dim3 grid((HC1 + 63) / 64, (NN + 63) / 64, 2);
        k_gemm64<true><<<grid, 128>>>((const __half*)p_xh, (const __half*)p_w1h,
                                      (float*)p_feat1, NN, HC1, FIN, FIN / 2);
    }
    k_att<C1><<<(NN * NH + T - 1) / T, T>>>((const float*)p_feat1, a1s, a1d,
                                            (float*)p_as1, (float*)p_ad1);
    k_agg<C1, true, false><<<NN, 256>>>((const float*)p_feat1, (const float*)p_as1,
                                        (const float*)p_ad1, b1,
                                        nullptr, (__half*)p_h1h);

    // layer 2: feat2 = h1h @ W2h
    {
        dim3 grid((HC2 + 63) / 64, (NN + 63) / 64, 1);
        k_gemm64<false><<<grid, 128>>>((const __half*)p_h1h, (const __half*)p_w2h,
                                       (float*)p_feat2, NN, HC2, HC1, HC1);
    }
    k_att<C2><<<(NN * NH + T - 1) / T, T>>>((const float*)p_feat2, a2s, a2d,
                                            (float*)p_as2, (float*)p_ad2);
    k_agg<C2, false, true><<<NN, 256>>>((const float*)p_feat2, (const float*)p_as2,
                                        (const float*)p_ad2, b2,
                                        out_h, (__half*)p_h2h);

    // final linear: out_cls(+bias init) += h2h @ Wlh  (split-K=4, atomic)
    {
        dim3 grid((NCLS + 63) / 64, (NN + 63) / 64, 4);
        k_gemm64<true><<<grid, 128>>>((const __half*)p_h2h, (const __half*)p_wlh,
                                      out_cls, NN, NCLS, HC2, HC2 / 4);
    }
}